// round 1
// baseline (speedup 1.0000x reference)
#include <cuda_runtime.h>

// Problem constants
#define BB 16
#define NN 256
#define HH 768
#define PP 2048
#define RR 3
#define MROWS (BB * NN)  // 4096

// Scratch (allocation is forbidden -> __device__ globals)
__device__ float g_head[MROWS * PP];        // 32 MB
__device__ float g_tail[MROWS * PP];        // 32 MB
__device__ float g_hw[RR * MROWS * PP];     // 96 MB

// ---------------------------------------------------------------------------
// Kernel 1: proj  C[4096,2048] = F[4096,768] * W[2048,768]^T + bias
// blockIdx.z = 0 -> head, 1 -> tail
// Tiles: BM=BN=128, BK=8, 256 threads, 8x8 per-thread micro-tile
// ---------------------------------------------------------------------------
__global__ __launch_bounds__(256, 2) void proj_kernel(
    const float* __restrict__ F,
    const float* __restrict__ hW, const float* __restrict__ hb,
    const float* __restrict__ tW, const float* __restrict__ tb)
{
    const float* W    = (blockIdx.z == 0) ? hW : tW;
    const float* bias = (blockIdx.z == 0) ? hb : tb;
    float* out        = (blockIdx.z == 0) ? g_head : g_tail;

    __shared__ float As[8][128];
    __shared__ float Bs[8][128];

    const int tid     = threadIdx.x;
    const int rowBase = blockIdx.y * 128;
    const int colBase = blockIdx.x * 128;

    const int ldRow = tid >> 1;        // 0..127
    const int ldCol = (tid & 1) * 4;   // 0 or 4

    const float* Aptr = F + (size_t)(rowBase + ldRow) * HH + ldCol;
    const float* Bptr = W + (size_t)(colBase + ldRow) * HH + ldCol;

    const int tx = tid & 15, ty = tid >> 4;
    const int m0 = ty * 8, n0 = tx * 8;

    float acc[8][8];
#pragma unroll
    for (int i = 0; i < 8; i++)
#pragma unroll
        for (int j = 0; j < 8; j++) acc[i][j] = 0.f;

    for (int k0 = 0; k0 < HH; k0 += 8) {
        float4 av = *(const float4*)(Aptr + k0);
        float4 bv = *(const float4*)(Bptr + k0);
        As[ldCol + 0][ldRow] = av.x; As[ldCol + 1][ldRow] = av.y;
        As[ldCol + 2][ldRow] = av.z; As[ldCol + 3][ldRow] = av.w;
        Bs[ldCol + 0][ldRow] = bv.x; Bs[ldCol + 1][ldRow] = bv.y;
        Bs[ldCol + 2][ldRow] = bv.z; Bs[ldCol + 3][ldRow] = bv.w;
        __syncthreads();
#pragma unroll
        for (int kk = 0; kk < 8; kk++) {
            float4 a0 = *(const float4*)&As[kk][m0];
            float4 a1 = *(const float4*)&As[kk][m0 + 4];
            float4 b0 = *(const float4*)&Bs[kk][n0];
            float4 b1 = *(const float4*)&Bs[kk][n0 + 4];
            float a[8] = {a0.x, a0.y, a0.z, a0.w, a1.x, a1.y, a1.z, a1.w};
            float b[8] = {b0.x, b0.y, b0.z, b0.w, b1.x, b1.y, b1.z, b1.w};
#pragma unroll
            for (int i = 0; i < 8; i++)
#pragma unroll
                for (int j = 0; j < 8; j++) acc[i][j] += a[i] * b[j];
        }
        __syncthreads();
    }

    float bv8[8];
#pragma unroll
    for (int j = 0; j < 8; j++) bv8[j] = __ldg(&bias[colBase + n0 + j]);

#pragma unroll
    for (int i = 0; i < 8; i++) {
        const int row = rowBase + m0 + i;
        float* orow = out + (size_t)row * PP + colBase + n0;
#pragma unroll
        for (int j = 0; j < 8; j += 4) {
            float4 v;
            v.x = acc[i][j + 0] + bv8[j + 0];
            v.y = acc[i][j + 1] + bv8[j + 1];
            v.z = acc[i][j + 2] + bv8[j + 2];
            v.w = acc[i][j + 3] + bv8[j + 3];
            *(float4*)(orow + j) = v;
        }
    }
}

// ---------------------------------------------------------------------------
// Kernel 2: hw  C_r[4096,2048] = head[4096,2048] * bil_W[r][2048,2048]  (NN)
// blockIdx.z = r
// ---------------------------------------------------------------------------
__global__ __launch_bounds__(256, 2) void hw_kernel(const float* __restrict__ bilW)
{
    const int r = blockIdx.z;
    const float* Bm = bilW + (size_t)r * PP * PP;
    float* out      = g_hw + (size_t)r * MROWS * PP;

    __shared__ float As[8][128];
    __shared__ float Bs[8][128];

    const int tid     = threadIdx.x;
    const int rowBase = blockIdx.y * 128;
    const int colBase = blockIdx.x * 128;

    const int ldRow = tid >> 1;
    const int ldCol = (tid & 1) * 4;
    const float* Aptr = g_head + (size_t)(rowBase + ldRow) * PP + ldCol;

    const int bk = tid >> 5;           // 0..7  (k row within tile)
    const int bn = (tid & 31) * 4;     // 0..124 (n offset)
    const float* Bptr = Bm + (size_t)bk * PP + colBase + bn;

    const int tx = tid & 15, ty = tid >> 4;
    const int m0 = ty * 8, n0 = tx * 8;

    float acc[8][8];
#pragma unroll
    for (int i = 0; i < 8; i++)
#pragma unroll
        for (int j = 0; j < 8; j++) acc[i][j] = 0.f;

    for (int k0 = 0; k0 < PP; k0 += 8) {
        float4 av = *(const float4*)(Aptr + k0);
        float4 bv = *(const float4*)(Bptr + (size_t)k0 * PP);
        As[ldCol + 0][ldRow] = av.x; As[ldCol + 1][ldRow] = av.y;
        As[ldCol + 2][ldRow] = av.z; As[ldCol + 3][ldRow] = av.w;
        *(float4*)&Bs[bk][bn] = bv;
        __syncthreads();
#pragma unroll
        for (int kk = 0; kk < 8; kk++) {
            float4 a0 = *(const float4*)&As[kk][m0];
            float4 a1 = *(const float4*)&As[kk][m0 + 4];
            float4 b0 = *(const float4*)&Bs[kk][n0];
            float4 b1 = *(const float4*)&Bs[kk][n0 + 4];
            float a[8] = {a0.x, a0.y, a0.z, a0.w, a1.x, a1.y, a1.z, a1.w};
            float b[8] = {b0.x, b0.y, b0.z, b0.w, b1.x, b1.y, b1.z, b1.w};
#pragma unroll
            for (int i = 0; i < 8; i++)
#pragma unroll
                for (int j = 0; j < 8; j++) acc[i][j] += a[i] * b[j];
        }
        __syncthreads();
    }

#pragma unroll
    for (int i = 0; i < 8; i++) {
        const int row = rowBase + m0 + i;
        float* orow = out + (size_t)row * PP + colBase + n0;
#pragma unroll
        for (int j = 0; j < 8; j += 4) {
            float4 v;
            v.x = acc[i][j + 0]; v.y = acc[i][j + 1];
            v.z = acc[i][j + 2]; v.w = acc[i][j + 3];
            *(float4*)(orow + j) = v;
        }
    }
}

// ---------------------------------------------------------------------------
// Kernel 3: logits[b,n,m,r] = sum_q hw[r, b*256+n, q] * tail[b*256+m, q] + bil_b[r]
// blockIdx.z = b * 3 + r; tiles 128x128 over (n, m), K = 2048, both K-contig (A*B^T)
// ---------------------------------------------------------------------------
__global__ __launch_bounds__(256, 2) void logits_kernel(
    const float* __restrict__ bilb, float* __restrict__ out)
{
    const int z = blockIdx.z;
    const int b = z / RR;
    const int r = z % RR;

    const float* A  = g_hw + ((size_t)r * MROWS + (size_t)b * NN) * PP;  // [256, 2048]
    const float* Bm = g_tail + (size_t)b * NN * PP;                      // [256, 2048]

    __shared__ float As[8][128];
    __shared__ float Bs[8][128];

    const int tid     = threadIdx.x;
    const int rowBase = blockIdx.y * 128;  // n
    const int colBase = blockIdx.x * 128;  // m

    const int ldRow = tid >> 1;
    const int ldCol = (tid & 1) * 4;
    const float* Aptr = A  + (size_t)(rowBase + ldRow) * PP + ldCol;
    const float* Bptr = Bm + (size_t)(colBase + ldRow) * PP + ldCol;

    const int tx = tid & 15, ty = tid >> 4;
    const int m0 = ty * 8, n0 = tx * 8;

    float acc[8][8];
#pragma unroll
    for (int i = 0; i < 8; i++)
#pragma unroll
        for (int j = 0; j < 8; j++) acc[i][j] = 0.f;

    for (int k0 = 0; k0 < PP; k0 += 8) {
        float4 av = *(const float4*)(Aptr + k0);
        float4 bv = *(const float4*)(Bptr + k0);
        As[ldCol + 0][ldRow] = av.x; As[ldCol + 1][ldRow] = av.y;
        As[ldCol + 2][ldRow] = av.z; As[ldCol + 3][ldRow] = av.w;
        Bs[ldCol + 0][ldRow] = bv.x; Bs[ldCol + 1][ldRow] = bv.y;
        Bs[ldCol + 2][ldRow] = bv.z; Bs[ldCol + 3][ldRow] = bv.w;
        __syncthreads();
#pragma unroll
        for (int kk = 0; kk < 8; kk++) {
            float4 a0 = *(const float4*)&As[kk][m0];
            float4 a1 = *(const float4*)&As[kk][m0 + 4];
            float4 b0 = *(const float4*)&Bs[kk][n0];
            float4 b1 = *(const float4*)&Bs[kk][n0 + 4];
            float a[8] = {a0.x, a0.y, a0.z, a0.w, a1.x, a1.y, a1.z, a1.w};
            float b[8] = {b0.x, b0.y, b0.z, b0.w, b1.x, b1.y, b1.z, b1.w};
#pragma unroll
            for (int i = 0; i < 8; i++)
#pragma unroll
                for (int j = 0; j < 8; j++) acc[i][j] += a[i] * b[j];
        }
        __syncthreads();
    }

    const float bb = __ldg(&bilb[r]);
#pragma unroll
    for (int i = 0; i < 8; i++) {
        const int n = rowBase + m0 + i;
        // out[((b*NN + n)*NN + m)*RR + r]
        float* obase = out + (((size_t)b * NN + n) * NN + colBase + n0) * RR + r;
#pragma unroll
        for (int j = 0; j < 8; j++) {
            obase[(size_t)j * RR] = acc[i][j] + bb;
        }
    }
}

// ---------------------------------------------------------------------------
// Launch
// Inputs: 0 features [16,256,768], 1 head_W [2048,768], 2 head_b [2048],
//         3 tail_W [2048,768], 4 tail_b [2048], 5 bil_W [3,2048,2048], 6 bil_b [3]
// Output: float32 [16,256,256,3]
// ---------------------------------------------------------------------------
extern "C" void kernel_launch(void* const* d_in, const int* in_sizes, int n_in,
                              void* d_out, int out_size)
{
    const float* features = (const float*)d_in[0];
    const float* head_W   = (const float*)d_in[1];
    const float* head_b   = (const float*)d_in[2];
    const float* tail_W   = (const float*)d_in[3];
    const float* tail_b   = (const float*)d_in[4];
    const float* bil_W    = (const float*)d_in[5];
    const float* bil_b    = (const float*)d_in[6];
    float* out = (float*)d_out;

    dim3 blk(256);

    // head & tail projections: grid (P/128, M/128, 2)
    proj_kernel<<<dim3(PP / 128, MROWS / 128, 2), blk>>>(
        features, head_W, head_b, tail_W, tail_b);

    // hw = head @ bil_W[r]: grid (P/128, M/128, 3)
    hw_kernel<<<dim3(PP / 128, MROWS / 128, RR), blk>>>(bil_W);

    // logits: grid (256/128, 256/128, B*R)
    logits_kernel<<<dim3(NN / 128, NN / 128, BB * RR), blk>>>(bil_b, out);
}

// round 2
// speedup vs baseline: 2.2680x; 2.2680x over previous
#include <cuda_runtime.h>

#define BB 16
#define NN 256
#define HH 768
#define PP 2048
#define RR 3
#define MROWS (BB * NN)  // 4096

// Scratch (__device__ globals; allocation forbidden)
__device__ float g_T1[RR * HH * PP];     // Wh^T Wr        [3,768,2048]
__device__ float g_M [RR * HH * HH];     // Wh^T Wr Wt     [3,768,768]
__device__ float g_G [RR * MROWS * HH];  // F @ M_r        [3,4096,768]
__device__ float g_w [RR * PP];          // Wr bt
__device__ float g_z [RR * PP];          // Wr^T bh
__device__ float g_u [RR * HH];          // Wh^T w
__device__ float g_v [RR * HH];          // Wt^T z
__device__ float g_fu[RR * MROWS];       // F u
__device__ float g_fv[RR * MROWS];       // F v
__device__ float g_s [RR];               // bh.w + bil_b

// ---------------------------------------------------------------------------
// Shared SGEMM core: 128x128 tile, BK=8, 256 threads, 8x8 micro-tile,
// double-buffered shared memory.
//  AT=false: A stored [K, M] (k rows contiguous in m)  -> direct stage
//  AT=true : A stored [M, K] (m rows contiguous in k)  -> transposed stage
//  BT analogous for B ([K, N] vs [N, K]).
// ---------------------------------------------------------------------------
__device__ __forceinline__ void mm_compute(const float (*As)[128], const float (*Bs)[128],
                                           int mm, int nn, float acc[8][8])
{
#pragma unroll
    for (int kk = 0; kk < 8; kk++) {
        float4 a0 = *(const float4*)&As[kk][mm];
        float4 a1 = *(const float4*)&As[kk][mm + 4];
        float4 b0 = *(const float4*)&Bs[kk][nn];
        float4 b1 = *(const float4*)&Bs[kk][nn + 4];
        float a[8] = {a0.x, a0.y, a0.z, a0.w, a1.x, a1.y, a1.z, a1.w};
        float b[8] = {b0.x, b0.y, b0.z, b0.w, b1.x, b1.y, b1.z, b1.w};
#pragma unroll
        for (int i = 0; i < 8; i++)
#pragma unroll
            for (int j = 0; j < 8; j++) acc[i][j] += a[i] * b[j];
    }
}

template<bool AT, bool BT>
__device__ __forceinline__ void gemm_core(const float* __restrict__ A, int lda,
                                          const float* __restrict__ B, int ldb,
                                          int K, int m0, int n0,
                                          int mm, int nn, float acc[8][8])
{
    __shared__ float As[2][8][128];
    __shared__ float Bs[2][8][128];
    const int tid = threadIdx.x;

    const int kr = tid >> 5;          // 0..7   (direct stage: k row)
    const int cc = (tid & 31) * 4;    // 0..124 (direct stage: m/n col)
    const int tr = tid >> 1;          // 0..127 (transposed stage: m/n row)
    const int tc = (tid & 1) * 4;     // 0 or 4 (transposed stage: k col)

    const float* Ap = AT ? (A + (size_t)(m0 + tr) * lda + tc)
                         : (A + (size_t)kr * lda + m0 + cc);
    const float* Bp = BT ? (B + (size_t)(n0 + tr) * ldb + tc)
                         : (B + (size_t)kr * ldb + n0 + cc);

    // prologue: tile 0
    float4 av = AT ? *(const float4*)(Ap) : *(const float4*)(Ap);
    float4 bv = BT ? *(const float4*)(Bp) : *(const float4*)(Bp);
    if (AT) { As[0][tc+0][tr]=av.x; As[0][tc+1][tr]=av.y; As[0][tc+2][tr]=av.z; As[0][tc+3][tr]=av.w; }
    else    { *(float4*)&As[0][kr][cc] = av; }
    if (BT) { Bs[0][tc+0][tr]=bv.x; Bs[0][tc+1][tr]=bv.y; Bs[0][tc+2][tr]=bv.z; Bs[0][tc+3][tr]=bv.w; }
    else    { *(float4*)&Bs[0][kr][cc] = bv; }
    __syncthreads();

    int buf = 0;
    for (int k0 = 8; k0 < K; k0 += 8) {
        av = AT ? *(const float4*)(Ap + k0) : *(const float4*)(Ap + (size_t)k0 * lda);
        bv = BT ? *(const float4*)(Bp + k0) : *(const float4*)(Bp + (size_t)k0 * ldb);

        mm_compute(As[buf], Bs[buf], mm, nn, acc);

        const int nb = buf ^ 1;
        if (AT) { As[nb][tc+0][tr]=av.x; As[nb][tc+1][tr]=av.y; As[nb][tc+2][tr]=av.z; As[nb][tc+3][tr]=av.w; }
        else    { *(float4*)&As[nb][kr][cc] = av; }
        if (BT) { Bs[nb][tc+0][tr]=bv.x; Bs[nb][tc+1][tr]=bv.y; Bs[nb][tc+2][tr]=bv.z; Bs[nb][tc+3][tr]=bv.w; }
        else    { *(float4*)&Bs[nb][kr][cc] = bv; }
        __syncthreads();
        buf = nb;
    }
    mm_compute(As[buf], Bs[buf], mm, nn, acc);
}

#define MICRO_IDX                                     \
    const int tid = threadIdx.x;                      \
    const int tx = tid & 15, ty = tid >> 4;           \
    const int mm = ty * 8, nn = tx * 8;               \
    float acc[8][8];                                  \
    _Pragma("unroll") for (int i = 0; i < 8; i++)     \
    _Pragma("unroll") for (int j = 0; j < 8; j++) acc[i][j] = 0.f;

// ---------------------------------------------------------------------------
// gemm1: T1_r[h,q] = sum_p Wh[p,h] * Wr[r,p,q]      M=768 N=2048 K=2048
// ---------------------------------------------------------------------------
__global__ __launch_bounds__(256, 2) void gemm1_kernel(
    const float* __restrict__ hW, const float* __restrict__ bilW)
{
    const int r  = blockIdx.z;
    const int m0 = blockIdx.y * 128;
    const int n0 = blockIdx.x * 128;
    MICRO_IDX;
    gemm_core<false, false>(hW, HH, bilW + (size_t)r * PP * PP, PP,
                            PP, m0, n0, mm, nn, acc);
    float* C = g_T1 + (size_t)r * HH * PP;
#pragma unroll
    for (int i = 0; i < 8; i++) {
        float* row = C + (size_t)(m0 + mm + i) * PP + n0 + nn;
#pragma unroll
        for (int j = 0; j < 8; j += 4)
            *(float4*)(row + j) = make_float4(acc[i][j], acc[i][j+1], acc[i][j+2], acc[i][j+3]);
    }
}

// ---------------------------------------------------------------------------
// gemm2: M_r[h,h2] = sum_q T1_r[h,q] * Wt[q,h2]     M=768 N=768 K=2048
// ---------------------------------------------------------------------------
__global__ __launch_bounds__(256, 2) void gemm2_kernel(const float* __restrict__ tW)
{
    const int r  = blockIdx.z;
    const int m0 = blockIdx.y * 128;
    const int n0 = blockIdx.x * 128;
    MICRO_IDX;
    gemm_core<true, false>(g_T1 + (size_t)r * HH * PP, PP, tW, HH,
                           PP, m0, n0, mm, nn, acc);
    float* C = g_M + (size_t)r * HH * HH;
#pragma unroll
    for (int i = 0; i < 8; i++) {
        float* row = C + (size_t)(m0 + mm + i) * HH + n0 + nn;
#pragma unroll
        for (int j = 0; j < 8; j += 4)
            *(float4*)(row + j) = make_float4(acc[i][j], acc[i][j+1], acc[i][j+2], acc[i][j+3]);
    }
}

// ---------------------------------------------------------------------------
// gemm3: G_r[n,h2] = sum_h F[n,h] * M_r[h,h2]       M=4096 N=768 K=768
// ---------------------------------------------------------------------------
__global__ __launch_bounds__(256, 2) void gemm3_kernel(const float* __restrict__ F)
{
    const int r  = blockIdx.z;
    const int m0 = blockIdx.y * 128;
    const int n0 = blockIdx.x * 128;
    MICRO_IDX;
    gemm_core<true, false>(F, HH, g_M + (size_t)r * HH * HH, HH,
                           HH, m0, n0, mm, nn, acc);
    float* C = g_G + (size_t)r * MROWS * HH;
#pragma unroll
    for (int i = 0; i < 8; i++) {
        float* row = C + (size_t)(m0 + mm + i) * HH + n0 + nn;
#pragma unroll
        for (int j = 0; j < 8; j += 4)
            *(float4*)(row + j) = make_float4(acc[i][j], acc[i][j+1], acc[i][j+2], acc[i][j+3]);
    }
}

// ---------------------------------------------------------------------------
// gemm4: logits[b,n,m,r] = sum_h G_r[b*256+n,h] * F[b*256+m,h]
//                          + fu[r,b*256+n] + fv[r,b*256+m] + s[r]
// grid (2, 2, B*R);  K = 768
// ---------------------------------------------------------------------------
__global__ __launch_bounds__(256, 2) void gemm4_kernel(
    const float* __restrict__ F, float* __restrict__ out)
{
    const int z = blockIdx.z;
    const int b = z / RR;
    const int r = z % RR;
    const int m0 = blockIdx.y * 128;  // n-dim of logits
    const int n0 = blockIdx.x * 128;  // m-dim of logits
    MICRO_IDX;
    gemm_core<true, true>(g_G + ((size_t)r * MROWS + (size_t)b * NN) * HH, HH,
                          F + (size_t)b * NN * HH, HH,
                          HH, m0, n0, mm, nn, acc);

    const float sv = g_s[r];
    const float* fu = g_fu + (size_t)r * MROWS + b * NN;
    const float* fv = g_fv + (size_t)r * MROWS + b * NN;
    float fvj[8];
#pragma unroll
    for (int j = 0; j < 8; j++) fvj[j] = fv[n0 + nn + j] + sv;

#pragma unroll
    for (int i = 0; i < 8; i++) {
        const int n = m0 + mm + i;
        const float fun = fu[n];
        float* obase = out + (((size_t)b * NN + n) * NN + n0 + nn) * RR + r;
#pragma unroll
        for (int j = 0; j < 8; j++)
            obase[(size_t)j * RR] = acc[i][j] + fun + fvj[j];
    }
}

// ---------------------------------------------------------------------------
// Small vector kernels
// ---------------------------------------------------------------------------
__global__ void vec_w_kernel(const float* __restrict__ bilW, const float* __restrict__ bt)
{
    const int r = blockIdx.y;
    const int warp = threadIdx.x >> 5, lane = threadIdx.x & 31;
    const int p = blockIdx.x * 8 + warp;
    const float* row = bilW + ((size_t)r * PP + p) * PP;
    float acc = 0.f;
    for (int q = lane; q < PP; q += 32) acc += row[q] * __ldg(&bt[q]);
#pragma unroll
    for (int o = 16; o; o >>= 1) acc += __shfl_down_sync(0xFFFFFFFFu, acc, o);
    if (lane == 0) g_w[r * PP + p] = acc;
}

__global__ void vec_z_kernel(const float* __restrict__ bilW, const float* __restrict__ bh)
{
    const int r = blockIdx.y;
    const int q = blockIdx.x * 256 + threadIdx.x;
    const float* base = bilW + (size_t)r * PP * PP + q;
    float acc = 0.f;
#pragma unroll 4
    for (int p = 0; p < PP; p++) acc += __ldg(&bh[p]) * base[(size_t)p * PP];
    g_z[r * PP + q] = acc;
}

__global__ void vec_s_kernel(const float* __restrict__ bh, const float* __restrict__ bilb)
{
    const int r = blockIdx.x;
    __shared__ float red[256];
    float acc = 0.f;
    for (int p = threadIdx.x; p < PP; p += 256) acc += bh[p] * g_w[r * PP + p];
    red[threadIdx.x] = acc;
    __syncthreads();
    for (int o = 128; o; o >>= 1) {
        if (threadIdx.x < o) red[threadIdx.x] += red[threadIdx.x + o];
        __syncthreads();
    }
    if (threadIdx.x == 0) g_s[r] = red[0] + bilb[r];
}

__global__ void vec_uv_kernel(const float* __restrict__ hW, const float* __restrict__ tW)
{
    const int sel = blockIdx.z;
    const int r = blockIdx.y;
    const int h = blockIdx.x * 256 + threadIdx.x;
    const float* Wm  = sel ? tW : hW;
    const float* vin = (sel ? g_z : g_w) + (size_t)r * PP;
    float acc = 0.f;
#pragma unroll 4
    for (int p = 0; p < PP; p++) acc += Wm[(size_t)p * HH + h] * vin[p];
    (sel ? g_v : g_u)[r * HH + h] = acc;
}

__global__ void vec_fufv_kernel(const float* __restrict__ F)
{
    const int sel = blockIdx.z;
    const int r = blockIdx.y;
    const int warp = threadIdx.x >> 5, lane = threadIdx.x & 31;
    const int n = blockIdx.x * 8 + warp;
    const float* f  = F + (size_t)n * HH;
    const float* vv = (sel ? g_v : g_u) + (size_t)r * HH;
    float acc = 0.f;
    for (int h = lane; h < HH; h += 32) acc += f[h] * vv[h];
#pragma unroll
    for (int o = 16; o; o >>= 1) acc += __shfl_down_sync(0xFFFFFFFFu, acc, o);
    if (lane == 0) (sel ? g_fv : g_fu)[r * MROWS + n] = acc;
}

// ---------------------------------------------------------------------------
// Launch
// ---------------------------------------------------------------------------
extern "C" void kernel_launch(void* const* d_in, const int* in_sizes, int n_in,
                              void* d_out, int out_size)
{
    const float* features = (const float*)d_in[0];
    const float* head_W   = (const float*)d_in[1];
    const float* head_b   = (const float*)d_in[2];
    const float* tail_W   = (const float*)d_in[3];
    const float* tail_b   = (const float*)d_in[4];
    const float* bil_W    = (const float*)d_in[5];
    const float* bil_b    = (const float*)d_in[6];
    float* out = (float*)d_out;

    dim3 blk(256);

    // bias-path vectors (cheap)
    vec_w_kernel <<<dim3(PP / 8, RR), blk>>>(bil_W, tail_b);
    vec_z_kernel <<<dim3(PP / 256, RR), blk>>>(bil_W, head_b);
    vec_s_kernel <<<dim3(RR), blk>>>(head_b, bil_b);
    vec_uv_kernel<<<dim3(HH / 256, RR, 2), blk>>>(head_W, tail_W);
    vec_fufv_kernel<<<dim3(MROWS / 8, RR, 2), blk>>>(features);

    // factored GEMM chain
    gemm1_kernel<<<dim3(PP / 128, HH / 128, RR), blk>>>(head_W, bil_W);
    gemm2_kernel<<<dim3(HH / 128, HH / 128, RR), blk>>>(tail_W);
    gemm3_kernel<<<dim3(HH / 128, MROWS / 128, RR), blk>>>(features);
    gemm4_kernel<<<dim3(NN / 128, NN / 128, BB * RR), blk>>>(features, out);
}

// round 3
// speedup vs baseline: 3.5958x; 1.5854x over previous
#include <cuda_runtime.h>

#define BB 16
#define NN 256
#define HH 768
#define PP 2048
#define RR 3
#define MROWS (BB * NN)  // 4096

typedef unsigned long long ull;

// Scratch (__device__ globals; allocation forbidden)
__device__ float g_T1 [RR * HH * PP];       // Wh^T Wr          [3,768,2048]
__device__ float g_Mp [2 * RR * HH * HH];   // gemm2 split-K partials
__device__ float g_M  [RR * HH * HH];       // Wh^T Wr Wt       [3,768,768]
__device__ float g_G  [RR * MROWS * HH];    // F @ M_r          [3,4096,768]
__device__ float g_w  [RR * PP];            // Wr bt
__device__ float g_zp [16 * RR * PP];       // z partials
__device__ float g_z  [RR * PP];            // Wr^T bh
__device__ float g_uvp[16 * RR * HH];       // u/v partials [sel*8+sp][r][h]
__device__ float g_uv [2 * RR * HH];        // u (sel=0), v (sel=1)
__device__ float g_fu [RR * MROWS];         // F u
__device__ float g_fv [RR * MROWS];         // F v
__device__ float g_s  [RR];                 // bh.w + bil_b

// ---------------------------------------------------------------------------
// Packed fp32x2 helpers
// ---------------------------------------------------------------------------
__device__ __forceinline__ ull ffma2(ull a, ull b, ull c) {
    ull d;
    asm("fma.rn.f32x2 %0, %1, %2, %3;" : "=l"(d) : "l"(a), "l"(b), "l"(c));
    return d;
}
__device__ __forceinline__ ull pack2(float x) {
    ull d;
    asm("mov.b64 %0, {%1, %1};" : "=l"(d) : "f"(x));
    return d;
}
__device__ __forceinline__ float2 unpk2(ull v) {
    float2 r;
    asm("mov.b64 {%0, %1}, %2;" : "=f"(r.x), "=f"(r.y) : "l"(v));
    return r;
}
union F4U { float4 f; ull u[2]; };

// ---------------------------------------------------------------------------
// SGEMM core: block tile 256(m) x 128(n), BK=8, 256 threads, 1 CTA/SM.
// Per-thread micro-tile 16x8 split as rows {ty*8..+7} u {128+ty*8..+7},
// cols {tx*4..+3} u {64+tx*4..+3}. Accumulators packed f32x2 along m.
//  AT=false: A stored [K, M];  AT=true: A stored [M, K].  BT analogous.
// ---------------------------------------------------------------------------
__device__ __forceinline__ void mm256(const float (*As)[256], const float (*Bs)[128],
                                      int ty, int tx, ull acc[8][8])
{
    const int ma0 = ty * 8, ma1 = 128 + ty * 8;
    const int na0 = tx * 4, na1 = 64 + tx * 4;
#pragma unroll
    for (int kk = 0; kk < 8; kk++) {
        F4U a0, a1, a2, a3;
        a0.f = *(const float4*)&As[kk][ma0];
        a1.f = *(const float4*)&As[kk][ma0 + 4];
        a2.f = *(const float4*)&As[kk][ma1];
        a3.f = *(const float4*)&As[kk][ma1 + 4];
        float4 b0 = *(const float4*)&Bs[kk][na0];
        float4 b1 = *(const float4*)&Bs[kk][na1];
        ull aa[8] = {a0.u[0], a0.u[1], a1.u[0], a1.u[1],
                     a2.u[0], a2.u[1], a3.u[0], a3.u[1]};
        ull bb[8] = {pack2(b0.x), pack2(b0.y), pack2(b0.z), pack2(b0.w),
                     pack2(b1.x), pack2(b1.y), pack2(b1.z), pack2(b1.w)};
#pragma unroll
        for (int mi = 0; mi < 8; mi++)
#pragma unroll
            for (int j = 0; j < 8; j++)
                acc[mi][j] = ffma2(aa[mi], bb[j], acc[mi][j]);
    }
}

template<bool AT, bool BT>
__device__ __forceinline__ void gemm_core(const float* __restrict__ A, int lda,
                                          const float* __restrict__ B, int ldb,
                                          int K, int m0, int n0,
                                          int ty, int tx, ull acc[8][8])
{
    __shared__ float As[2][8][256];
    __shared__ float Bs[2][8][128];
    const int tid = threadIdx.x;

    // direct-stage indices ([K, *]: k row, contiguous cols)
    const int akr = tid >> 5, acol = (tid & 31) * 8;   // A: 32 thr x 8 floats
    const int bkr = tid >> 5, bcol = (tid & 31) * 4;   // B: 32 thr x 4 floats
    // transposed-stage indices ([*, K]: row per thread(s), contiguous k)
    const int btr = tid >> 1, btc = (tid & 1) * 4;     // B: 128 rows x (2 thr x 4 k)

    const float* Ap = AT ? (A + (size_t)(m0 + tid) * lda)
                         : (A + (size_t)akr * lda + m0 + acol);
    const float* Bp = BT ? (B + (size_t)(n0 + btr) * ldb + btc)
                         : (B + (size_t)bkr * ldb + n0 + bcol);

    float4 av0, av1, bv;
    // prologue: stage tile 0
    if (AT) { av0 = *(const float4*)(Ap); av1 = *(const float4*)(Ap + 4); }
    else    { av0 = *(const float4*)(Ap); av1 = *(const float4*)(Ap + 4); }
    bv = *(const float4*)(Bp);
    if (AT) {
        As[0][0][tid] = av0.x; As[0][1][tid] = av0.y; As[0][2][tid] = av0.z; As[0][3][tid] = av0.w;
        As[0][4][tid] = av1.x; As[0][5][tid] = av1.y; As[0][6][tid] = av1.z; As[0][7][tid] = av1.w;
    } else {
        *(float4*)&As[0][akr][acol] = av0; *(float4*)&As[0][akr][acol + 4] = av1;
    }
    if (BT) {
        Bs[0][btc + 0][btr] = bv.x; Bs[0][btc + 1][btr] = bv.y;
        Bs[0][btc + 2][btr] = bv.z; Bs[0][btc + 3][btr] = bv.w;
    } else {
        *(float4*)&Bs[0][bkr][bcol] = bv;
    }
    __syncthreads();

    int buf = 0;
    for (int k0 = 8; k0 < K; k0 += 8) {
        if (AT) { av0 = *(const float4*)(Ap + k0); av1 = *(const float4*)(Ap + k0 + 4); }
        else    { av0 = *(const float4*)(Ap + (size_t)k0 * lda);
                  av1 = *(const float4*)(Ap + (size_t)k0 * lda + 4); }
        bv = BT ? *(const float4*)(Bp + k0) : *(const float4*)(Bp + (size_t)k0 * ldb);

        mm256(As[buf], Bs[buf], ty, tx, acc);

        const int nb = buf ^ 1;
        if (AT) {
            As[nb][0][tid] = av0.x; As[nb][1][tid] = av0.y; As[nb][2][tid] = av0.z; As[nb][3][tid] = av0.w;
            As[nb][4][tid] = av1.x; As[nb][5][tid] = av1.y; As[nb][6][tid] = av1.z; As[nb][7][tid] = av1.w;
        } else {
            *(float4*)&As[nb][akr][acol] = av0; *(float4*)&As[nb][akr][acol + 4] = av1;
        }
        if (BT) {
            Bs[nb][btc + 0][btr] = bv.x; Bs[nb][btc + 1][btr] = bv.y;
            Bs[nb][btc + 2][btr] = bv.z; Bs[nb][btc + 3][btr] = bv.w;
        } else {
            *(float4*)&Bs[nb][bkr][bcol] = bv;
        }
        __syncthreads();
        buf = nb;
    }
    mm256(As[buf], Bs[buf], ty, tx, acc);
}

#define MICRO_IDX                                   \
    const int tid = threadIdx.x;                    \
    const int tx = tid & 15, ty = tid >> 4;         \
    ull acc[8][8];                                  \
    _Pragma("unroll") for (int i = 0; i < 8; i++)   \
    _Pragma("unroll") for (int j = 0; j < 8; j++) acc[i][j] = 0ull;

__device__ __forceinline__ int mrow_of(int mi, int ty) {
    return (mi < 4) ? (ty * 8 + 2 * mi) : (128 + ty * 8 + 2 * (mi - 4));
}

// Plain row-major epilogue: C[row, col], ldc given.
__device__ __forceinline__ void store_plain(float* C, int ldc, int m0, int n0,
                                            int ty, int tx, const ull acc[8][8])
{
    const int na0 = n0 + tx * 4, na1 = n0 + 64 + tx * 4;
#pragma unroll
    for (int mi = 0; mi < 8; mi++) {
        const int row = m0 + mrow_of(mi, ty);
        float2 p[8];
#pragma unroll
        for (int j = 0; j < 8; j++) p[j] = unpk2(acc[mi][j]);
        float* r0 = C + (size_t)row * ldc;
        float* r1 = C + (size_t)(row + 1) * ldc;
        *(float4*)(r0 + na0) = make_float4(p[0].x, p[1].x, p[2].x, p[3].x);
        *(float4*)(r0 + na1) = make_float4(p[4].x, p[5].x, p[6].x, p[7].x);
        *(float4*)(r1 + na0) = make_float4(p[0].y, p[1].y, p[2].y, p[3].y);
        *(float4*)(r1 + na1) = make_float4(p[4].y, p[5].y, p[6].y, p[7].y);
    }
}

// ---------------------------------------------------------------------------
// gemm1: T1_r[h,q] = sum_p Wh[p,h] * Wr[r,p,q]   M=768 N=2048 K=2048
// grid (16, 3, 3)
// ---------------------------------------------------------------------------
__global__ __launch_bounds__(256, 1) void gemm1_kernel(
    const float* __restrict__ hW, const float* __restrict__ bilW)
{
    const int r  = blockIdx.z;
    const int m0 = blockIdx.y * 256;
    const int n0 = blockIdx.x * 128;
    MICRO_IDX;
    gemm_core<false, false>(hW, HH, bilW + (size_t)r * PP * PP, PP,
                            PP, m0, n0, ty, tx, acc);
    store_plain(g_T1 + (size_t)r * HH * PP, PP, m0, n0, ty, tx, acc);
}

// ---------------------------------------------------------------------------
// gemm2 (split-K=2): Mp[kh][r][h,h2] = sum_{q in half} T1_r[h,q] * Wt[q,h2]
// M=768 N=768 K=1024.  grid (6, 3, 6) with z = r*2 + kh
// ---------------------------------------------------------------------------
__global__ __launch_bounds__(256, 1) void gemm2_kernel(const float* __restrict__ tW)
{
    const int z  = blockIdx.z;
    const int r  = z >> 1;
    const int kh = z & 1;
    const int m0 = blockIdx.y * 256;
    const int n0 = blockIdx.x * 128;
    MICRO_IDX;
    gemm_core<true, false>(g_T1 + (size_t)r * HH * PP + kh * 1024, PP,
                           tW + (size_t)kh * 1024 * HH, HH,
                           1024, m0, n0, ty, tx, acc);
    store_plain(g_Mp + ((size_t)kh * RR + r) * HH * HH, HH, m0, n0, ty, tx, acc);
}

__global__ void reduceM_kernel() {
    const int i = blockIdx.x * 256 + threadIdx.x;  // float4 index
    const float4 a = *((const float4*)g_Mp + i);
    const float4 b = *((const float4*)g_Mp + (size_t)RR * HH * HH / 4 + i);
    *((float4*)g_M + i) = make_float4(a.x + b.x, a.y + b.y, a.z + b.z, a.w + b.w);
}

// ---------------------------------------------------------------------------
// gemm3: G_r[n,h2] = sum_h F[n,h] * M_r[h,h2]    M=4096 N=768 K=768
// grid (6, 16, 3)
// ---------------------------------------------------------------------------
__global__ __launch_bounds__(256, 1) void gemm3_kernel(const float* __restrict__ F)
{
    const int r  = blockIdx.z;
    const int m0 = blockIdx.y * 256;
    const int n0 = blockIdx.x * 128;
    MICRO_IDX;
    gemm_core<true, false>(F, HH, g_M + (size_t)r * HH * HH, HH,
                           HH, m0, n0, ty, tx, acc);
    store_plain(g_G + (size_t)r * MROWS * HH, HH, m0, n0, ty, tx, acc);
}

// ---------------------------------------------------------------------------
// gemm4: logits[b,n,m,r] = sum_h G_r[b*256+n,h]*F[b*256+m,h] + fu + fv + s
// M=256 N=256 K=768.  grid (2, 1, 48) with z = b*RR + r
// ---------------------------------------------------------------------------
__global__ __launch_bounds__(256, 1) void gemm4_kernel(
    const float* __restrict__ F, float* __restrict__ out)
{
    const int z = blockIdx.z;
    const int b = z / RR;
    const int r = z % RR;
    const int n0 = blockIdx.x * 128;  // logits m-dim
    MICRO_IDX;
    gemm_core<true, true>(g_G + ((size_t)r * MROWS + (size_t)b * NN) * HH, HH,
                          F + (size_t)b * NN * HH, HH,
                          HH, 0, n0, ty, tx, acc);

    const float sv = g_s[r];
    const float* fu = g_fu + (size_t)r * MROWS + b * NN;
    const float* fv = g_fv + (size_t)r * MROWS + b * NN;

    const int na0 = n0 + tx * 4, na1 = n0 + 64 + tx * 4;
    float fvj[8];
#pragma unroll
    for (int j = 0; j < 4; j++) { fvj[j] = fv[na0 + j] + sv; fvj[j + 4] = fv[na1 + j] + sv; }

#pragma unroll
    for (int mi = 0; mi < 8; mi++) {
        const int n = mrow_of(mi, ty);
        const float fu0 = fu[n], fu1 = fu[n + 1];
        float2 p[8];
#pragma unroll
        for (int j = 0; j < 8; j++) p[j] = unpk2(acc[mi][j]);
        float* o0 = out + (((size_t)b * NN + n) * NN) * RR + r;
        float* o1 = o0 + (size_t)NN * RR;
#pragma unroll
        for (int j = 0; j < 4; j++) {
            o0[(size_t)(na0 + j) * RR] = p[j].x + fu0 + fvj[j];
            o0[(size_t)(na1 + j) * RR] = p[j + 4].x + fu0 + fvj[j + 4];
            o1[(size_t)(na0 + j) * RR] = p[j].y + fu1 + fvj[j];
            o1[(size_t)(na1 + j) * RR] = p[j + 4].y + fu1 + fvj[j + 4];
        }
    }
}

// ---------------------------------------------------------------------------
// Vector stage (all deterministic: fixed-shape partials + tree reduces)
// ---------------------------------------------------------------------------
// w[r,p] = sum_q W[r,p,q] * bt[q].  grid (PP/8, RR), 8 warps x 1 row each
__global__ void vec_w_kernel(const float* __restrict__ bilW, const float* __restrict__ bt)
{
    const int r = blockIdx.y;
    const int warp = threadIdx.x >> 5, lane = threadIdx.x & 31;
    const int p = blockIdx.x * 8 + warp;
    const float* row = bilW + ((size_t)r * PP + p) * PP;
    float acc = 0.f;
    for (int q = lane; q < PP; q += 32) acc += row[q] * __ldg(&bt[q]);
#pragma unroll
    for (int o = 16; o; o >>= 1) acc += __shfl_down_sync(0xFFFFFFFFu, acc, o);
    if (lane == 0) g_w[r * PP + p] = acc;
}

// z partials over p-chunks of 128.  grid (PP/256, RR, 16)
__global__ void vec_z_part(const float* __restrict__ bilW, const float* __restrict__ bh)
{
    const int r = blockIdx.y, sp = blockIdx.z;
    const int q = blockIdx.x * 256 + threadIdx.x;
    const float* base = bilW + (size_t)r * PP * PP + (size_t)sp * 128 * PP + q;
    float acc = 0.f;
#pragma unroll 4
    for (int p = 0; p < 128; p++) acc += __ldg(&bh[sp * 128 + p]) * base[(size_t)p * PP];
    g_zp[((size_t)sp * RR + r) * PP + q] = acc;
}

__global__ void reduce_z() {
    const int o = blockIdx.x * 256 + threadIdx.x;  // [RR*PP)
    float acc = 0.f;
#pragma unroll
    for (int sp = 0; sp < 16; sp++) acc += g_zp[(size_t)sp * RR * PP + o];
    g_z[o] = acc;
}

// s[r] = bh . w[r] + bil_b[r]
__global__ void vec_s_kernel(const float* __restrict__ bh, const float* __restrict__ bilb)
{
    const int r = blockIdx.x;
    __shared__ float red[256];
    float acc = 0.f;
    for (int p = threadIdx.x; p < PP; p += 256) acc += bh[p] * g_w[r * PP + p];
    red[threadIdx.x] = acc;
    __syncthreads();
    for (int o = 128; o; o >>= 1) {
        if (threadIdx.x < o) red[threadIdx.x] += red[threadIdx.x + o];
        __syncthreads();
    }
    if (threadIdx.x == 0) g_s[r] = red[0] + bilb[r];
}

// u/v partials over p-chunks of 256.  grid (HH/256, RR, 16): z = sel*8 + sp
__global__ void vec_uv_part(const float* __restrict__ hW, const float* __restrict__ tW)
{
    const int sel = blockIdx.z >> 3, sp = blockIdx.z & 7;
    const int r = blockIdx.y;
    const int h = blockIdx.x * 256 + threadIdx.x;
    const float* Wm  = sel ? tW : hW;
    const float* vin = (sel ? g_z : g_w) + (size_t)r * PP + sp * 256;
    const float* base = Wm + (size_t)sp * 256 * HH + h;
    float acc = 0.f;
#pragma unroll 4
    for (int p = 0; p < 256; p++) acc += base[(size_t)p * HH] * __ldg(&vin[p]);
    g_uvp[((size_t)(sel * 8 + sp) * RR + r) * HH + h] = acc;
}

__global__ void reduce_uv() {
    const int o = blockIdx.x * 256 + threadIdx.x;      // [2*RR*HH)
    const int sel = o / (RR * HH);
    const int rem = o % (RR * HH);
    float acc = 0.f;
#pragma unroll
    for (int sp = 0; sp < 8; sp++) acc += g_uvp[((size_t)(sel * 8 + sp) * RR * HH) + rem];
    g_uv[o] = acc;
}

// fu[r,n] = F[n,:] . u[r];  fv[r,n] = F[n,:] . v[r].  grid (MROWS/8, RR, 2)
__global__ void vec_fufv_kernel(const float* __restrict__ F)
{
    const int sel = blockIdx.z;
    const int r = blockIdx.y;
    const int warp = threadIdx.x >> 5, lane = threadIdx.x & 31;
    const int n = blockIdx.x * 8 + warp;
    const float* f  = F + (size_t)n * HH;
    const float* vv = g_uv + ((size_t)sel * RR + r) * HH;
    float acc = 0.f;
    for (int h = lane; h < HH; h += 32) acc += f[h] * __ldg(&vv[h]);
#pragma unroll
    for (int o = 16; o; o >>= 1) acc += __shfl_down_sync(0xFFFFFFFFu, acc, o);
    if (lane == 0) (sel ? g_fv : g_fu)[r * MROWS + n] = acc;
}

// ---------------------------------------------------------------------------
// Launch
// ---------------------------------------------------------------------------
extern "C" void kernel_launch(void* const* d_in, const int* in_sizes, int n_in,
                              void* d_out, int out_size)
{
    const float* features = (const float*)d_in[0];
    const float* head_W   = (const float*)d_in[1];
    const float* head_b   = (const float*)d_in[2];
    const float* tail_W   = (const float*)d_in[3];
    const float* tail_b   = (const float*)d_in[4];
    const float* bil_W    = (const float*)d_in[5];
    const float* bil_b    = (const float*)d_in[6];
    float* out = (float*)d_out;

    dim3 blk(256);

    // vector/bias path (deterministic partials)
    vec_w_kernel  <<<dim3(PP / 8, RR), blk>>>(bil_W, tail_b);
    vec_z_part    <<<dim3(PP / 256, RR, 16), blk>>>(bil_W, head_b);
    reduce_z      <<<dim3(RR * PP / 256), blk>>>();
    vec_s_kernel  <<<dim3(RR), blk>>>(head_b, bil_b);
    vec_uv_part   <<<dim3(HH / 256, RR, 16), blk>>>(head_W, tail_W);
    reduce_uv     <<<dim3(2 * RR * HH / 256), blk>>>();
    vec_fufv_kernel<<<dim3(MROWS / 8, RR, 2), blk>>>(features);

    // factored GEMM chain
    gemm1_kernel  <<<dim3(PP / 128, HH / 256, RR), blk>>>(head_W, bil_W);
    gemm2_kernel  <<<dim3(HH / 128, HH / 256, RR * 2), blk>>>(tail_W);
    reduceM_kernel<<<dim3(RR * HH * HH / 4 / 256), blk>>>();
    gemm3_kernel  <<<dim3(HH / 128, MROWS / 256, RR), blk>>>(features);
    gemm4_kernel  <<<dim3(NN / 128, NN / 256, BB * RR), blk>>>(features, out);
}